// round 14
// baseline (speedup 1.0000x reference)
#include <cuda_runtime.h>
#include <cuda_fp16.h>
#include <cstdint>

#define HH 64
#define WW 64
#define PP 4096          // HH*WW
#define CC 21
#define CPAD 24
#define NB 2
#define KS 71
#define KR 35
#define SPLITS 4
#define KRANGE (PP / SPLITS)   // 1024
#define BM 64
#define KC 64
#define NCH (KRANGE / KC)      // 16
#define STAGES 3
#define A_BYTES   8192         // Kh 64x64 halves
#define A8_BYTES  4096         // Kl fp8 64x64 (permuted)
#define B_BYTES   3072         // V 64x24 halves
// stage layout: [Ah 0][Al8 8192][Bh 12288][Bl 15360]
#define STAGE_BYTES (A_BYTES + A8_BYTES + 2 * B_BYTES)   // 18432
#define SMEM_DYN (STAGES * STAGE_BYTES)                  // 55296
#define LO_SCALE 2.44140625e-4f                          // 2^-12

// ---------------- scratch (static device globals; no allocation) ----------------
// Kh tiled: [n][pb][qc][64*64] halves, 8KB/tile, segment-swizzled.
// Kl8 tiled: [n][pb][qc][4096B], fragment-permuted: warp*1024 + kk*256 + lane*8 + byte.
__device__ __align__(16) __half  d_Kth[(size_t)NB * PP * PP];
__device__ __align__(16) uint8_t d_Ktl8[(size_t)NB * PP * PP];
__device__ __align__(16) float   d_feats[NB * PP * 5];
__device__ __align__(16) float   d_U[NB * CC * PP];
__device__ __align__(16) float   d_q[NB * CC * PP];
__device__ __align__(16) __half  d_Vh[(size_t)NB * PP * CPAD];
__device__ __align__(16) __half  d_Vl[(size_t)NB * PP * CPAD];
__device__ __align__(16) float   d_qbfp[(size_t)SPLITS * NB * CC * PP];
__device__ __align__(16) float   d_tmp[NB * CC * PP];
__device__ float                 d_g1d[KS];

// ---------------- async helpers ----------------
#define CP_BULK_EL(dst_s, src_g, nbytes, mbar_s, pol) \
    asm volatile("cp.async.bulk.shared::cta.global.mbarrier::complete_tx::bytes.L2::cache_hint" \
        " [%0], [%1], %2, [%3], %4;" \
        :: "r"(dst_s), "l"(src_g), "r"(nbytes), "r"(mbar_s), "l"(pol) : "memory")
#define MBAR_INIT(mbar_s, cnt) \
    asm volatile("mbarrier.init.shared.b64 [%0], %1;" :: "r"(mbar_s), "r"(cnt) : "memory")
#define MBAR_EXPECT_TX(mbar_s, tx) \
    asm volatile("mbarrier.arrive.expect_tx.shared.b64 _, [%0], %1;" :: "r"(mbar_s), "r"(tx) : "memory")
#define MBAR_ARRIVE(mbar_s) \
    asm volatile("mbarrier.arrive.shared.b64 _, [%0];" :: "r"(mbar_s) : "memory")
#define MBAR_WAIT(mbar_s, parity) do { \
    asm volatile( \
        "{\n\t.reg .pred P;\n\t" \
        "WAIT_%=:\n\t" \
        "mbarrier.try_wait.parity.acquire.cta.shared::cta.b64 P, [%0], %1, 0x989680;\n\t" \
        "@P bra.uni DONE_%=;\n\t" \
        "bra.uni WAIT_%=;\n\t" \
        "DONE_%=:\n\t}" \
        :: "r"(mbar_s), "r"(parity) : "memory"); \
} while (0)

__device__ __forceinline__ uint64_t policy_evict_last() {
    uint64_t p;
    asm("createpolicy.fractional.L2::evict_last.b64 %0, 1.0;" : "=l"(p));
    return p;
}
__device__ __forceinline__ uint64_t policy_evict_first() {
    uint64_t p;
    asm("createpolicy.fractional.L2::evict_first.b64 %0, 1.0;" : "=l"(p));
    return p;
}

__device__ __forceinline__ void split_half(float v, __half& hi, __half& lo) {
    hi = __float2half(v);
    lo = __float2half(v - __half2float(hi));
}

// ---------------- fused prep: g1d + feats + U/softmax/V ----------------
__global__ void prep_kernel(const float* __restrict__ unary,
                            const float* __restrict__ ref,
                            const float* __restrict__ gk,
                            const float* __restrict__ kstd) {
    int idx = blockIdx.x * blockDim.x + threadIdx.x;
    if (blockIdx.x == 0 && threadIdx.x < KS) {
        float center = gk[KR * KS + KR];
        d_g1d[threadIdx.x] = gk[threadIdx.x * KS + KR] * rsqrtf(center);
    }
    if (idx >= NB * PP) return;
    int n = idx / PP, p = idx % PP;
    int y = p / WW, x = p % WW;

    const float* r = ref + (size_t)n * 3 * PP + p;
    d_feats[idx * 5 + 0] = (float)y / kstd[0];
    d_feats[idx * 5 + 1] = (float)x / kstd[1];
    d_feats[idx * 5 + 2] = r[0]        / kstd[2];
    d_feats[idx * 5 + 3] = r[PP]       / kstd[3];
    d_feats[idx * 5 + 4] = r[2 * PP]   / kstd[4];

    const float* u = unary + (size_t)n * CC * PP + p;
    float lg[CC];
    float m = -1e30f;
    #pragma unroll
    for (int c = 0; c < CC; ++c) {
        float v = u[(size_t)c * PP];
        v = fminf(fmaxf(v, 1e-5f), 1.0f);
        v = logf(v);
        lg[c] = v;
        m = fmaxf(m, v);
        d_U[((size_t)n * CC + c) * PP + p] = v;
    }
    float s = 0.f;
    #pragma unroll
    for (int c = 0; c < CC; ++c) { float e = expf(lg[c] - m); lg[c] = e; s += e; }
    float inv = 1.f / s;
    __half* vh = d_Vh + ((size_t)n * PP + p) * CPAD;
    __half* vl = d_Vl + ((size_t)n * PP + p) * CPAD;
    #pragma unroll
    for (int c = 0; c < CC; ++c) {
        float qv = lg[c] * inv;
        d_q[((size_t)n * CC + c) * PP + p] = qv;
        split_half(qv, vh[c], vl[c]);
    }
    #pragma unroll
    for (int c = CC; c < CPAD; ++c) { vh[c] = __float2half(0.f); vl[c] = __float2half(0.f); }
}

// ---------------- build K: Kh fp16 swizzled tiles + Kl fp8 permuted tiles ----------------
// Stores tagged L2::evict_last so K stays resident for all 5 GEMM iterations.
__global__ __launch_bounds__(256) void buildK_kernel() {
    __shared__ float fpS[64][5];
    __shared__ float fqS[64][5];
    int n  = blockIdx.z;
    int pb = blockIdx.y;
    int qc = blockIdx.x;
    int tid = threadIdx.x;

    for (int i = tid; i < 320; i += 256) {
        (&fpS[0][0])[i] = d_feats[((size_t)n * PP + pb * 64) * 5 + i];
        (&fqS[0][0])[i] = d_feats[((size_t)n * PP + qc * 64) * 5 + i];
    }
    __syncthreads();

    uint64_t pol = policy_evict_last();

    int seg = tid & 7;       // q segment (8 cols)
    int pr0 = tid >> 3;      // rows pr0 and pr0+32
    int q0  = seg << 3;
    int kk  = seg >> 1;      // k16 index within tile
    int up  = seg & 1;       // upper 8 cols of the k16

    float qf0[8], qf1[8], qf2[8], qf3[8], qf4[8];
    #pragma unroll
    for (int j = 0; j < 8; ++j) {
        qf0[j] = fqS[q0 + j][0];
        qf1[j] = fqS[q0 + j][1];
        qf2[j] = fqS[q0 + j][2];
        qf3[j] = fqS[q0 + j][3];
        qf4[j] = fqS[q0 + j][4];
    }

    uint32_t tbase  = ((uint32_t)(n * 64 + pb) * 64 + (uint32_t)qc) << 12;  // halves
    uint32_t t8base = ((uint32_t)(n * 64 + pb) * 64 + (uint32_t)qc) << 12;  // bytes

    #pragma unroll
    for (int rr = 0; rr < 2; ++rr) {
        int pr = pr0 + rr * 32;
        int gid    = pr & 7;
        int half_r = (pr >> 3) & 1;
        int warp_g = pr >> 4;
        float b0 = fpS[pr][0], b1 = fpS[pr][1], b2 = fpS[pr][2],
              b3 = fpS[pr][3], b4 = fpS[pr][4];
        __align__(16) __half hbuf[8];
        float lof[8];
        #pragma unroll
        for (int j = 0; j < 8; ++j) {
            float x0 = b0 - qf0[j], x1 = b1 - qf1[j], x2 = b2 - qf2[j],
                  x3 = b3 - qf3[j], x4 = b4 - qf4[j];
            float dd = x0*x0 + x1*x1 + x2*x2 + x3*x3 + x4*x4;
            float k  = __expf(-0.5f * dd);
            __half hi = __float2half(k);
            hbuf[j] = hi;
            lof[j] = (k - __half2float(hi)) * 4096.0f;
        }
        uint32_t off = tbase + ((uint32_t)pr << 6) + ((uint32_t)(seg ^ (pr & 7)) << 3);
        {
            const uint32_t* hw = (const uint32_t*)hbuf;
            asm volatile("st.global.L2::cache_hint.v4.b32 [%0], {%1,%2,%3,%4}, %5;"
                :: "l"(d_Kth + off), "r"(hw[0]), "r"(hw[1]), "r"(hw[2]), "r"(hw[3]), "l"(pol)
                : "memory");
        }

        // fp8 lo, fragment-permuted: byte = (q&1) + 2*half_r + 4*up
        uint32_t base8 = t8base + (uint32_t)warp_g * 1024u + (uint32_t)kk * 256u
                       + (uint32_t)(2 * half_r + 4 * up);
        #pragma unroll
        for (int jj = 0; jj < 4; ++jj) {
            unsigned short pk;
            asm("cvt.rn.satfinite.e4m3x2.f32 %0, %1, %2;"
                : "=h"(pk) : "f"(lof[2 * jj + 1]), "f"(lof[2 * jj]));
            asm volatile("st.global.L2::cache_hint.u16 [%0], %1, %2;"
                :: "l"(d_Ktl8 + base8 + (uint32_t)(gid * 4 + jj) * 8u), "h"(pk), "l"(pol)
                : "memory");
        }
    }
}

// ---- GEMM: qbf[c,p] = sum_q K[p,q]*V[q,c]; Kh fp16 + Kl fp8(x2^12), V hi+lo fp16 ----
// K loads carry L2::evict_last; partial stores carry L2::evict_first.
__global__ __launch_bounds__(128) void gemm_kernel() {
    extern __shared__ __align__(16) char dynsm[];
    __shared__ __align__(8) uint64_t mb_full[STAGES];
    __shared__ __align__(8) uint64_t mb_empty[STAGES];

    int n   = blockIdx.z;
    int spl = blockIdx.y;
    int pb  = blockIdx.x;
    int p0  = pb * BM;
    int qc0 = spl * (KRANGE / 64);
    int tid = threadIdx.x;
    int warp = tid >> 5, lane = tid & 31;

    uint32_t dynbase = (uint32_t)__cvta_generic_to_shared(dynsm);
    uint64_t polL = policy_evict_last();

    uint32_t full_s[STAGES], empty_s[STAGES];
    #pragma unroll
    for (int s = 0; s < STAGES; ++s) {
        full_s[s]  = (uint32_t)__cvta_generic_to_shared(&mb_full[s]);
        empty_s[s] = (uint32_t)__cvta_generic_to_shared(&mb_empty[s]);
    }
    if (tid == 0) {
        #pragma unroll
        for (int s = 0; s < STAGES; ++s) { MBAR_INIT(full_s[s], 1); MBAR_INIT(empty_s[s], 128); }
    }
    __syncthreads();

    const char* Ktile_h = (const char*)(d_Kth + (((((size_t)n * 64 + pb) * 64) + qc0) << 12));
    const char* Ktile_8 = (const char*)(d_Ktl8 + (((((size_t)n * 64 + pb) * 64) + qc0) << 12));
    const char* Vh_g = (const char*)(d_Vh + ((size_t)n * PP + spl * KRANGE) * CPAD);
    const char* Vl_g = (const char*)(d_Vl + ((size_t)n * PP + spl * KRANGE) * CPAD);

    auto issue = [&](int ch) {
        int s = ch % STAGES;
        uint32_t sb = dynbase + s * STAGE_BYTES;
        MBAR_EXPECT_TX(full_s[s], (uint32_t)STAGE_BYTES);
        CP_BULK_EL(sb,                       Ktile_h + (size_t)ch * A_BYTES,  A_BYTES,  full_s[s], polL);
        CP_BULK_EL(sb + A_BYTES,             Ktile_8 + (size_t)ch * A8_BYTES, A8_BYTES, full_s[s], polL);
        CP_BULK_EL(sb + A_BYTES + A8_BYTES,  Vh_g + (size_t)ch * B_BYTES,     B_BYTES,  full_s[s], polL);
        CP_BULK_EL(sb + A_BYTES + A8_BYTES + B_BYTES, Vl_g + (size_t)ch * B_BYTES, B_BYTES, full_s[s], polL);
    };

    if (tid == 0) {
        #pragma unroll
        for (int s = 0; s < STAGES; ++s) issue(s);
    }

    float acc[3][4], accl[3][4];
    #pragma unroll
    for (int i = 0; i < 3; ++i)
        #pragma unroll
        for (int j = 0; j < 4; ++j) { acc[i][j] = 0.f; accl[i][j] = 0.f; }

    int m0 = warp * 16;
    for (int ch = 0; ch < NCH; ++ch) {
        int s = ch % STAGES;
        int u = ch / STAGES;
        MBAR_WAIT(full_s[s], u & 1);
        uint32_t sb = dynbase + s * STAGE_BYTES;

        #pragma unroll
        for (int kk = 0; kk < KC / 16; ++kk) {
            int arow = m0 + (lane & 15);
            int aseg = (kk * 2 + (lane >> 4)) ^ (arow & 7);
            uint32_t aaddr_h = sb + arow * 128 + aseg * 16;
            uint32_t ah0, ah1, ah2, ah3;
            asm volatile("ldmatrix.sync.aligned.m8n8.x4.shared.b16 {%0,%1,%2,%3}, [%4];"
                         : "=r"(ah0), "=r"(ah1), "=r"(ah2), "=r"(ah3) : "r"(aaddr_h));

            // fp8 lo fragment: contiguous 8 bytes per thread, then cvt to 4 f16x2 regs
            uint32_t aaddr_8 = sb + A_BYTES + warp * 1024 + kk * 256 + lane * 8;
            uint32_t w0, w1;
            asm volatile("ld.shared.v2.u32 {%0,%1}, [%2];" : "=r"(w0), "=r"(w1) : "r"(aaddr_8));
            unsigned short s0 = (unsigned short)w0, s1 = (unsigned short)(w0 >> 16);
            unsigned short s2 = (unsigned short)w1, s3 = (unsigned short)(w1 >> 16);
            uint32_t al0, al1, al2, al3;
            asm("cvt.rn.f16x2.e4m3x2 %0, %1;" : "=r"(al0) : "h"(s0));
            asm("cvt.rn.f16x2.e4m3x2 %0, %1;" : "=r"(al1) : "h"(s1));
            asm("cvt.rn.f16x2.e4m3x2 %0, %1;" : "=r"(al2) : "h"(s2));
            asm("cvt.rn.f16x2.e4m3x2 %0, %1;" : "=r"(al3) : "h"(s3));

            #pragma unroll
            for (int nt = 0; nt < 3; ++nt) {
                uint32_t baddr_h = sb + A_BYTES + A8_BYTES + (kk * 16 + (lane & 15)) * 48 + nt * 16;
                uint32_t baddr_l = baddr_h + B_BYTES;
                uint32_t bh0, bh1, bl0, bl1;
                asm volatile("ldmatrix.sync.aligned.m8n8.x2.trans.shared.b16 {%0,%1}, [%2];"
                             : "=r"(bh0), "=r"(bh1) : "r"(baddr_h));
                asm volatile("ldmatrix.sync.aligned.m8n8.x2.trans.shared.b16 {%0,%1}, [%2];"
                             : "=r"(bl0), "=r"(bl1) : "r"(baddr_l));
                asm volatile(
                    "mma.sync.aligned.m16n8k16.row.col.f32.f16.f16.f32 "
                    "{%0,%1,%2,%3}, {%4,%5,%6,%7}, {%8,%9}, {%0,%1,%2,%3};"
                    : "+f"(acc[nt][0]), "+f"(acc[nt][1]), "+f"(acc[nt][2]), "+f"(acc[nt][3])
                    : "r"(ah0), "r"(ah1), "r"(ah2), "r"(ah3), "r"(bh0), "r"(bh1));
                asm volatile(
                    "mma.sync.aligned.m16n8k16.row.col.f32.f16.f16.f32 "
                    "{%0,%1,%2,%3}, {%4,%5,%6,%7}, {%8,%9}, {%0,%1,%2,%3};"
                    : "+f"(acc[nt][0]), "+f"(acc[nt][1]), "+f"(acc[nt][2]), "+f"(acc[nt][3])
                    : "r"(ah0), "r"(ah1), "r"(ah2), "r"(ah3), "r"(bl0), "r"(bl1));
                asm volatile(
                    "mma.sync.aligned.m16n8k16.row.col.f32.f16.f16.f32 "
                    "{%0,%1,%2,%3}, {%4,%5,%6,%7}, {%8,%9}, {%0,%1,%2,%3};"
                    : "+f"(accl[nt][0]), "+f"(accl[nt][1]), "+f"(accl[nt][2]), "+f"(accl[nt][3])
                    : "r"(al0), "r"(al1), "r"(al2), "r"(al3), "r"(bh0), "r"(bh1));
            }
        }

        MBAR_ARRIVE(empty_s[s]);
        if (tid == 0 && ch + STAGES < NCH) {
            MBAR_WAIT(empty_s[s], u & 1);
            issue(ch + STAGES);
        }
    }

    // epilogue: scatter partials (hi accum + scaled lo accum), evict_first stores
    uint64_t polF = policy_evict_first();
    float* qbf = d_qbfp + ((size_t)(spl * NB + n) * CC) * PP;
    int prow = p0 + warp * 16 + (lane >> 2);
    int cb = (lane & 3) * 2;
    #pragma unroll
    for (int nt = 0; nt < 3; ++nt)
        #pragma unroll
        for (int r = 0; r < 4; ++r) {
            int c = nt * 8 + cb + (r & 1);
            int p = prow + (r >> 1) * 8;
            if (c < CC) {
                float v = acc[nt][r] + LO_SCALE * accl[nt][r];
                asm volatile("st.global.L2::cache_hint.f32 [%0], %1, %2;"
                    :: "l"(qbf + (size_t)c * PP + p), "f"(v), "l"(polF) : "memory");
            }
        }
}

// ---------------- vertical 1-D conv on q -> tmp ----------------
__global__ void vconv_kernel() {
    int idx = blockIdx.x * blockDim.x + threadIdx.x;
    if (idx >= NB * CC * PP) return;
    int x = idx & 63, y = (idx >> 6) & 63, nc = idx >> 12;
    const float* base = d_q + (size_t)nc * PP;
    int dlo = (35 - y) > 0 ? (35 - y) : 0;
    int dhi = (98 - y) < 70 ? (98 - y) : 70;
    float acc = 0.f;
    for (int d = dlo; d <= dhi; ++d)
        acc += d_g1d[d] * base[(y + d - KR) * WW + x];
    d_tmp[idx] = acc;
}

// ---------------- horizontal conv + combine + softmax (128 threads) ----------------
__global__ __launch_bounds__(128) void hcombine_kernel(float* __restrict__ outp, int write_out) {
    __shared__ float row[CC][WW + 2 * KR];
    __shared__ float comb[CC][WW];
    __shared__ float g[KS];
    int bn = blockIdx.x;
    int n = bn >> 6, y = bn & 63;
    int tid = threadIdx.x;

    for (int i = tid; i < KS; i += 128) g[i] = d_g1d[i];
    {
        int x = tid & 63, h = tid >> 6;
        for (int c = h; c < CC; c += 2) {
            row[c][KR + x] = d_tmp[((size_t)n * CC + c) * PP + y * WW + x];
            if (x < KR) { row[c][x] = 0.f; row[c][KR + WW + x] = 0.f; }
        }
    }
    __syncthreads();

    const size_t SPL = (size_t)NB * CC * PP;
    for (int o = tid; o < CC * WW; o += 128) {
        int c = o >> 6, x = o & 63;
        float s = 0.f;
        #pragma unroll 7
        for (int d = 0; d < KS; ++d) s += g[d] * row[c][x + d];
        size_t pidx = (size_t)(n * CC + c) * PP + y * WW + x;
        float qb = d_qbfp[pidx] + d_qbfp[SPL + pidx]
                 + d_qbfp[2 * SPL + pidx] + d_qbfp[3 * SPL + pidx];
        comb[c][x] = d_U[pidx] + 4.0f * qb + 2.0f * s;
    }
    __syncthreads();

    if (tid < 64) {
        int x = tid;
        float lg[CC];
        float m = -1e30f;
        #pragma unroll
        for (int c = 0; c < CC; ++c) { lg[c] = comb[c][x]; m = fmaxf(m, lg[c]); }
        float ssum = 0.f;
        #pragma unroll
        for (int c = 0; c < CC; ++c) { float e = expf(lg[c] - m); lg[c] = e; ssum += e; }
        float inv = 1.f / ssum;
        __half* vh = d_Vh + ((size_t)n * PP + y * WW + x) * CPAD;
        __half* vl = d_Vl + ((size_t)n * PP + y * WW + x) * CPAD;
        #pragma unroll
        for (int c = 0; c < CC; ++c) {
            float qv = lg[c] * inv;
            size_t o = ((size_t)n * CC + c) * PP + y * WW + x;
            d_q[o] = qv;
            split_half(qv, vh[c], vl[c]);
            if (write_out) outp[o] = qv;
        }
    }
}

// ---------------- launch ----------------
extern "C" void kernel_launch(void* const* d_in, const int* in_sizes, int n_in,
                              void* d_out, int out_size) {
    const float* unary = (const float*)d_in[0];
    const float* ref   = (const float*)d_in[1];
    const float* gk    = (const float*)d_in[2];
    const float* kstd  = (const float*)d_in[3];
    float* out = (float*)d_out;

    cudaFuncSetAttribute(gemm_kernel, cudaFuncAttributeMaxDynamicSharedMemorySize, SMEM_DYN);

    prep_kernel<<<(NB * PP + 255) / 256, 256>>>(unary, ref, gk, kstd);
    buildK_kernel<<<dim3(64, 64, NB), 256>>>();

    for (int it = 0; it < 5; ++it) {
        vconv_kernel<<<(NB * CC * PP + 255) / 256, 256>>>();
        gemm_kernel<<<dim3(PP / BM, SPLITS, NB), 128, SMEM_DYN>>>();
        hcombine_kernel<<<NB * HH, 128>>>(out, it == 4 ? 1 : 0);
    }
}

// round 15
// speedup vs baseline: 1.0401x; 1.0401x over previous
#include <cuda_runtime.h>
#include <cuda_fp16.h>
#include <cstdint>

#define HH 64
#define WW 64
#define PP 4096          // HH*WW
#define CC 21
#define NB 2
#define KS 71
#define KR 35
#define SPLITS 8
#define KRANGE (PP / SPLITS)   // 512
#define BM 64
#define KC 64
#define NCH (KRANGE / KC)      // 8
#define STAGES 2
#define KT_BYTES 12288         // combined tile: Kh 8192 + Kl8 4096
#define V_BYTES  6144          // combined V chunk: hi 3072 + lo 3072
#define STAGE_BYTES (KT_BYTES + V_BYTES)   // 18432
#define SMEM_DYN (STAGES * STAGE_BYTES)    // 36864
#define LO_SCALE 2.44140625e-4f            // 2^-12

// ---------------- scratch (static device globals; no allocation) ----------------
// Combined K tile [n][pb][qc] (12288B): [Kh 64x64 fp16 swizzled][Kl8 4096B fragment-permuted]
__device__ __align__(16) uint8_t d_Kt[(size_t)NB * 64 * 64 * KT_BYTES];
// Combined V chunk [n][chunk64] (6144B): [hi 64x24 fp16][lo 64x24 fp16]
__device__ __align__(16) uint8_t d_V[(size_t)NB * 64 * V_BYTES];
__device__ __align__(16) float   d_feats[NB * PP * 5];
__device__ __align__(16) float   d_U[NB * CC * PP];
__device__ __align__(16) float   d_q[NB * CC * PP];
__device__ __align__(16) float   d_qbfp[(size_t)SPLITS * NB * CC * PP];
__device__ __align__(16) float   d_tmp[NB * CC * PP];
__device__ float                 d_g1d[KS];

// ---------------- async helpers ----------------
#define CP_BULK(dst_s, src_g, nbytes, mbar_s) \
    asm volatile("cp.async.bulk.shared::cta.global.mbarrier::complete_tx::bytes [%0], [%1], %2, [%3];" \
        :: "r"(dst_s), "l"(src_g), "r"(nbytes), "r"(mbar_s) : "memory")
#define MBAR_INIT(mbar_s, cnt) \
    asm volatile("mbarrier.init.shared.b64 [%0], %1;" :: "r"(mbar_s), "r"(cnt) : "memory")
#define MBAR_EXPECT_TX(mbar_s, tx) \
    asm volatile("mbarrier.arrive.expect_tx.shared.b64 _, [%0], %1;" :: "r"(mbar_s), "r"(tx) : "memory")
#define MBAR_ARRIVE(mbar_s) \
    asm volatile("mbarrier.arrive.shared.b64 _, [%0];" :: "r"(mbar_s) : "memory")
#define MBAR_WAIT(mbar_s, parity) do { \
    asm volatile( \
        "{\n\t.reg .pred P;\n\t" \
        "WAIT_%=:\n\t" \
        "mbarrier.try_wait.parity.acquire.cta.shared::cta.b64 P, [%0], %1, 0x989680;\n\t" \
        "@P bra.uni DONE_%=;\n\t" \
        "bra.uni WAIT_%=;\n\t" \
        "DONE_%=:\n\t}" \
        :: "r"(mbar_s), "r"(parity) : "memory"); \
} while (0)

__device__ __forceinline__ void split_half(float v, __half& hi, __half& lo) {
    hi = __float2half(v);
    lo = __float2half(v - __half2float(hi));
}

// V combined addressing: pixel p, channel c (c < 24)
__device__ __forceinline__ uint8_t* v_hi_ptr(int n, int p, int c) {
    return d_V + (size_t)(n * 64 + (p >> 6)) * V_BYTES + ((p & 63) * 24 + c) * 2;
}
__device__ __forceinline__ uint8_t* v_lo_ptr(int n, int p, int c) {
    return v_hi_ptr(n, p, c) + 3072;
}

// ---------------- fused prep: g1d + feats + U/softmax/V ----------------
__global__ void prep_kernel(const float* __restrict__ unary,
                            const float* __restrict__ ref,
                            const float* __restrict__ gk,
                            const float* __restrict__ kstd) {
    int idx = blockIdx.x * blockDim.x + threadIdx.x;
    if (blockIdx.x == 0 && threadIdx.x < KS) {
        float center = gk[KR * KS + KR];
        d_g1d[threadIdx.x] = gk[threadIdx.x * KS + KR] * rsqrtf(center);
    }
    if (idx >= NB * PP) return;
    int n = idx / PP, p = idx % PP;
    int y = p / WW, x = p % WW;

    const float* r = ref + (size_t)n * 3 * PP + p;
    d_feats[idx * 5 + 0] = (float)y / kstd[0];
    d_feats[idx * 5 + 1] = (float)x / kstd[1];
    d_feats[idx * 5 + 2] = r[0]        / kstd[2];
    d_feats[idx * 5 + 3] = r[PP]       / kstd[3];
    d_feats[idx * 5 + 4] = r[2 * PP]   / kstd[4];

    const float* u = unary + (size_t)n * CC * PP + p;
    float lg[CC];
    float m = -1e30f;
    #pragma unroll
    for (int c = 0; c < CC; ++c) {
        float v = u[(size_t)c * PP];
        v = fminf(fmaxf(v, 1e-5f), 1.0f);
        v = logf(v);
        lg[c] = v;
        m = fmaxf(m, v);
        d_U[((size_t)n * CC + c) * PP + p] = v;
    }
    float s = 0.f;
    #pragma unroll
    for (int c = 0; c < CC; ++c) { float e = expf(lg[c] - m); lg[c] = e; s += e; }
    float inv = 1.f / s;
    #pragma unroll
    for (int c = 0; c < CC; ++c) {
        float qv = lg[c] * inv;
        d_q[((size_t)n * CC + c) * PP + p] = qv;
        __half hi, lo;
        split_half(qv, hi, lo);
        *(__half*)v_hi_ptr(n, p, c) = hi;
        *(__half*)v_lo_ptr(n, p, c) = lo;
    }
    #pragma unroll
    for (int c = CC; c < 24; ++c) {
        *(__half*)v_hi_ptr(n, p, c) = __float2half(0.f);
        *(__half*)v_lo_ptr(n, p, c) = __float2half(0.f);
    }
}

// ---------------- build K: combined tiles (Kh fp16 swizzled + Kl8 fp8 permuted) ----------------
__global__ __launch_bounds__(256) void buildK_kernel() {
    __shared__ float fpS[64][5];
    __shared__ float fqS[64][5];
    int n  = blockIdx.z;
    int pb = blockIdx.y;
    int qc = blockIdx.x;
    int tid = threadIdx.x;

    for (int i = tid; i < 320; i += 256) {
        (&fpS[0][0])[i] = d_feats[((size_t)n * PP + pb * 64) * 5 + i];
        (&fqS[0][0])[i] = d_feats[((size_t)n * PP + qc * 64) * 5 + i];
    }
    __syncthreads();

    int seg = tid & 7;       // q segment (8 cols)
    int pr0 = tid >> 3;      // rows pr0 and pr0+32
    int q0  = seg << 3;
    int kk  = seg >> 1;      // k16 index within tile
    int up  = seg & 1;       // upper 8 cols of the k16

    float qf0[8], qf1[8], qf2[8], qf3[8], qf4[8];
    #pragma unroll
    for (int j = 0; j < 8; ++j) {
        qf0[j] = fqS[q0 + j][0];
        qf1[j] = fqS[q0 + j][1];
        qf2[j] = fqS[q0 + j][2];
        qf3[j] = fqS[q0 + j][3];
        qf4[j] = fqS[q0 + j][4];
    }

    uint8_t* tileb = d_Kt + (size_t)((n * 64 + pb) * 64 + qc) * KT_BYTES;

    #pragma unroll
    for (int rr = 0; rr < 2; ++rr) {
        int pr = pr0 + rr * 32;
        int gid    = pr & 7;
        int half_r = (pr >> 3) & 1;
        int warp_g = pr >> 4;
        float b0 = fpS[pr][0], b1 = fpS[pr][1], b2 = fpS[pr][2],
              b3 = fpS[pr][3], b4 = fpS[pr][4];
        __align__(16) __half hbuf[8];
        float lof[8];
        #pragma unroll
        for (int j = 0; j < 8; ++j) {
            float x0 = b0 - qf0[j], x1 = b1 - qf1[j], x2 = b2 - qf2[j],
                  x3 = b3 - qf3[j], x4 = b4 - qf4[j];
            float dd = x0*x0 + x1*x1 + x2*x2 + x3*x3 + x4*x4;
            float k  = __expf(-0.5f * dd);
            __half hi = __float2half(k);
            hbuf[j] = hi;
            lof[j] = (k - __half2float(hi)) * 4096.0f;
        }
        *(uint4*)(tileb + pr * 128 + ((seg ^ (pr & 7)) << 4)) = *(const uint4*)hbuf;

        // fp8 lo, fragment-permuted at tile offset 8192
        uint32_t base8 = 8192u + (uint32_t)warp_g * 1024u + (uint32_t)kk * 256u
                       + (uint32_t)(2 * half_r + 4 * up);
        #pragma unroll
        for (int jj = 0; jj < 4; ++jj) {
            unsigned short pk;
            asm("cvt.rn.satfinite.e4m3x2.f32 %0, %1, %2;"
                : "=h"(pk) : "f"(lof[2 * jj + 1]), "f"(lof[2 * jj]));
            *(unsigned short*)(tileb + base8 + (uint32_t)(gid * 4 + jj) * 8u) = pk;
        }
    }
}

// ---- GEMM: qbf[c,p] = sum_q K[p,q]*V[q,c]; Kh fp16 + Kl fp8(x2^12), V hi+lo fp16 ----
// 2-stage ring, 2 bulk loads per chunk (combined K tile + combined V chunk).
__global__ __launch_bounds__(128) void gemm_kernel() {
    extern __shared__ __align__(16) char dynsm[];
    __shared__ __align__(8) uint64_t mb_full[STAGES];
    __shared__ __align__(8) uint64_t mb_empty[STAGES];

    int n   = blockIdx.z;
    int spl = blockIdx.y;
    int pb  = blockIdx.x;
    int p0  = pb * BM;
    int qc0 = spl * NCH;
    int tid = threadIdx.x;
    int warp = tid >> 5, lane = tid & 31;

    uint32_t dynbase = (uint32_t)__cvta_generic_to_shared(dynsm);

    uint32_t full_s[STAGES], empty_s[STAGES];
    #pragma unroll
    for (int s = 0; s < STAGES; ++s) {
        full_s[s]  = (uint32_t)__cvta_generic_to_shared(&mb_full[s]);
        empty_s[s] = (uint32_t)__cvta_generic_to_shared(&mb_empty[s]);
    }
    if (tid == 0) {
        #pragma unroll
        for (int s = 0; s < STAGES; ++s) { MBAR_INIT(full_s[s], 1); MBAR_INIT(empty_s[s], 128); }
    }
    __syncthreads();

    const uint8_t* Ksrc = d_Kt + (size_t)((n * 64 + pb) * 64 + qc0) * KT_BYTES;
    const uint8_t* Vsrc = d_V + (size_t)(n * 64 + qc0) * V_BYTES;

    auto issue = [&](int ch) {
        int s = ch % STAGES;
        uint32_t sb = dynbase + s * STAGE_BYTES;
        MBAR_EXPECT_TX(full_s[s], (uint32_t)STAGE_BYTES);
        CP_BULK(sb,            Ksrc + (size_t)ch * KT_BYTES, KT_BYTES, full_s[s]);
        CP_BULK(sb + KT_BYTES, Vsrc + (size_t)ch * V_BYTES,  V_BYTES,  full_s[s]);
    };

    if (tid == 0) {
        #pragma unroll
        for (int s = 0; s < STAGES; ++s) issue(s);
    }

    float acc[3][4], accl[3][4];
    #pragma unroll
    for (int i = 0; i < 3; ++i)
        #pragma unroll
        for (int j = 0; j < 4; ++j) { acc[i][j] = 0.f; accl[i][j] = 0.f; }

    int m0 = warp * 16;
    for (int ch = 0; ch < NCH; ++ch) {
        int s = ch % STAGES;
        int u = ch / STAGES;
        MBAR_WAIT(full_s[s], u & 1);
        uint32_t sb = dynbase + s * STAGE_BYTES;

        #pragma unroll
        for (int kk = 0; kk < KC / 16; ++kk) {
            int arow = m0 + (lane & 15);
            int aseg = (kk * 2 + (lane >> 4)) ^ (arow & 7);
            uint32_t aaddr_h = sb + arow * 128 + aseg * 16;
            uint32_t ah0, ah1, ah2, ah3;
            asm volatile("ldmatrix.sync.aligned.m8n8.x4.shared.b16 {%0,%1,%2,%3}, [%4];"
                         : "=r"(ah0), "=r"(ah1), "=r"(ah2), "=r"(ah3) : "r"(aaddr_h));

            uint32_t aaddr_8 = sb + 8192 + warp * 1024 + kk * 256 + lane * 8;
            uint32_t w0, w1;
            asm volatile("ld.shared.v2.u32 {%0,%1}, [%2];" : "=r"(w0), "=r"(w1) : "r"(aaddr_8));
            unsigned short s0 = (unsigned short)w0, s1 = (unsigned short)(w0 >> 16);
            unsigned short s2 = (unsigned short)w1, s3 = (unsigned short)(w1 >> 16);
            uint32_t al0, al1, al2, al3;
            asm("cvt.rn.f16x2.e4m3x2 %0, %1;" : "=r"(al0) : "h"(s0));
            asm("cvt.rn.f16x2.e4m3x2 %0, %1;" : "=r"(al1) : "h"(s1));
            asm("cvt.rn.f16x2.e4m3x2 %0, %1;" : "=r"(al2) : "h"(s2));
            asm("cvt.rn.f16x2.e4m3x2 %0, %1;" : "=r"(al3) : "h"(s3));

            #pragma unroll
            for (int nt = 0; nt < 3; ++nt) {
                uint32_t baddr_h = sb + KT_BYTES + (kk * 16 + (lane & 15)) * 48 + nt * 16;
                uint32_t baddr_l = baddr_h + 3072;
                uint32_t bh0, bh1, bl0, bl1;
                asm volatile("ldmatrix.sync.aligned.m8n8.x2.trans.shared.b16 {%0,%1}, [%2];"
                             : "=r"(bh0), "=r"(bh1) : "r"(baddr_h));
                asm volatile("ldmatrix.sync.aligned.m8n8.x2.trans.shared.b16 {%0,%1}, [%2];"
                             : "=r"(bl0), "=r"(bl1) : "r"(baddr_l));
                asm volatile(
                    "mma.sync.aligned.m16n8k16.row.col.f32.f16.f16.f32 "
                    "{%0,%1,%2,%3}, {%4,%5,%6,%7}, {%8,%9}, {%0,%1,%2,%3};"
                    : "+f"(acc[nt][0]), "+f"(acc[nt][1]), "+f"(acc[nt][2]), "+f"(acc[nt][3])
                    : "r"(ah0), "r"(ah1), "r"(ah2), "r"(ah3), "r"(bh0), "r"(bh1));
                asm volatile(
                    "mma.sync.aligned.m16n8k16.row.col.f32.f16.f16.f32 "
                    "{%0,%1,%2,%3}, {%4,%5,%6,%7}, {%8,%9}, {%0,%1,%2,%3};"
                    : "+f"(acc[nt][0]), "+f"(acc[nt][1]), "+f"(acc[nt][2]), "+f"(acc[nt][3])
                    : "r"(ah0), "r"(ah1), "r"(ah2), "r"(ah3), "r"(bl0), "r"(bl1));
                asm volatile(
                    "mma.sync.aligned.m16n8k16.row.col.f32.f16.f16.f32 "
                    "{%0,%1,%2,%3}, {%4,%5,%6,%7}, {%8,%9}, {%0,%1,%2,%3};"
                    : "+f"(accl[nt][0]), "+f"(accl[nt][1]), "+f"(accl[nt][2]), "+f"(accl[nt][3])
                    : "r"(al0), "r"(al1), "r"(al2), "r"(al3), "r"(bh0), "r"(bh1));
            }
        }

        MBAR_ARRIVE(empty_s[s]);
        if (tid == 0 && ch + STAGES < NCH) {
            MBAR_WAIT(empty_s[s], u & 1);
            issue(ch + STAGES);
        }
    }

    // epilogue: scatter partials (hi accum + scaled lo accum)
    float* qbf = d_qbfp + ((size_t)(spl * NB + n) * CC) * PP;
    int prow = p0 + warp * 16 + (lane >> 2);
    int cb = (lane & 3) * 2;
    #pragma unroll
    for (int nt = 0; nt < 3; ++nt)
        #pragma unroll
        for (int r = 0; r < 4; ++r) {
            int c = nt * 8 + cb + (r & 1);
            int p = prow + (r >> 1) * 8;
            if (c < CC) qbf[(size_t)c * PP + p] = acc[nt][r] + LO_SCALE * accl[nt][r];
        }
}

// ---------------- vertical 1-D conv on q -> tmp ----------------
__global__ void vconv_kernel() {
    int idx = blockIdx.x * blockDim.x + threadIdx.x;
    if (idx >= NB * CC * PP) return;
    int x = idx & 63, y = (idx >> 6) & 63, nc = idx >> 12;
    const float* base = d_q + (size_t)nc * PP;
    int dlo = (35 - y) > 0 ? (35 - y) : 0;
    int dhi = (98 - y) < 70 ? (98 - y) : 70;
    float acc = 0.f;
    for (int d = dlo; d <= dhi; ++d)
        acc += d_g1d[d] * base[(y + d - KR) * WW + x];
    d_tmp[idx] = acc;
}

// ---------------- horizontal conv + combine + softmax (128 threads) ----------------
__global__ __launch_bounds__(128) void hcombine_kernel(float* __restrict__ outp, int write_out) {
    __shared__ float row[CC][WW + 2 * KR];
    __shared__ float comb[CC][WW];
    __shared__ float g[KS];
    int bn = blockIdx.x;
    int n = bn >> 6, y = bn & 63;
    int tid = threadIdx.x;

    for (int i = tid; i < KS; i += 128) g[i] = d_g1d[i];
    {
        int x = tid & 63, h = tid >> 6;
        for (int c = h; c < CC; c += 2) {
            row[c][KR + x] = d_tmp[((size_t)n * CC + c) * PP + y * WW + x];
            if (x < KR) { row[c][x] = 0.f; row[c][KR + WW + x] = 0.f; }
        }
    }
    __syncthreads();

    const size_t SPL = (size_t)NB * CC * PP;
    for (int o = tid; o < CC * WW; o += 128) {
        int c = o >> 6, x = o & 63;
        float s = 0.f;
        #pragma unroll 7
        for (int d = 0; d < KS; ++d) s += g[d] * row[c][x + d];
        size_t pidx = (size_t)(n * CC + c) * PP + y * WW + x;
        float qb = 0.f;
        #pragma unroll
        for (int sp = 0; sp < SPLITS; ++sp)
            qb += d_qbfp[sp * SPL + pidx];
        comb[c][x] = d_U[pidx] + 4.0f * qb + 2.0f * s;
    }
    __syncthreads();

    if (tid < 64) {
        int x = tid;
        int p = y * WW + x;
        float lg[CC];
        float m = -1e30f;
        #pragma unroll
        for (int c = 0; c < CC; ++c) { lg[c] = comb[c][x]; m = fmaxf(m, lg[c]); }
        float ssum = 0.f;
        #pragma unroll
        for (int c = 0; c < CC; ++c) { float e = expf(lg[c] - m); lg[c] = e; ssum += e; }
        float inv = 1.f / ssum;
        #pragma unroll
        for (int c = 0; c < CC; ++c) {
            float qv = lg[c] * inv;
            size_t o = ((size_t)n * CC + c) * PP + p;
            d_q[o] = qv;
            __half hi, lo;
            split_half(qv, hi, lo);
            *(__half*)v_hi_ptr(n, p, c) = hi;
            *(__half*)v_lo_ptr(n, p, c) = lo;
            if (write_out) outp[o] = qv;
        }
    }
}

// ---------------- launch ----------------
extern "C" void kernel_launch(void* const* d_in, const int* in_sizes, int n_in,
                              void* d_out, int out_size) {
    const float* unary = (const float*)d_in[0];
    const float* ref   = (const float*)d_in[1];
    const float* gk    = (const float*)d_in[2];
    const float* kstd  = (const float*)d_in[3];
    float* out = (float*)d_out;

    cudaFuncSetAttribute(gemm_kernel, cudaFuncAttributeMaxDynamicSharedMemorySize, SMEM_DYN);

    prep_kernel<<<(NB * PP + 255) / 256, 256>>>(unary, ref, gk, kstd);
    buildK_kernel<<<dim3(64, 64, NB), 256>>>();

    for (int it = 0; it < 5; ++it) {
        vconv_kernel<<<(NB * CC * PP + 255) / 256, 256>>>();
        gemm_kernel<<<dim3(PP / BM, SPLITS, NB), 128, SMEM_DYN>>>();
        hcombine_kernel<<<NB * HH, 128>>>(out, it == 4 ? 1 : 0);
    }
}

// round 16
// speedup vs baseline: 1.3458x; 1.2940x over previous
#include <cuda_runtime.h>
#include <cuda_fp16.h>
#include <cstdint>

#define HH 64
#define WW 64
#define PP 4096          // HH*WW
#define CC 21
#define NB 2
#define KS 71
#define KR 35
#define SPLITS 8
#define KRANGE (PP / SPLITS)   // 512
#define BM 64
#define KC 64
#define NCH (KRANGE / KC)      // 8
#define STAGES 2
#define KT_BYTES 16384         // [Kh fp16 8192][fp8 own 4096][fp8 mirror 4096]
#define V_BYTES  6144          // [hi 64x24 fp16][lo 64x24 fp16]
#define STAGE_BYTES (8192 + 4096 + V_BYTES)   // 18432
#define SMEM_DYN (STAGES * STAGE_BYTES)       // 36864
#define LO_SCALE 2.44140625e-4f               // 2^-12

// ---------------- scratch (static device globals; no allocation) ----------------
// Symmetric K: tiles only for (a<=b); tile(a,b) = K[a-block rows][b-block cols].
__device__ __align__(16) uint8_t d_Kt[(size_t)NB * 64 * 64 * KT_BYTES];
__device__ __align__(16) uint8_t d_V[(size_t)NB * 64 * V_BYTES];
__device__ __align__(16) float   d_feats[NB * PP * 5];
__device__ __align__(16) float   d_U[NB * CC * PP];
__device__ __align__(16) float   d_q[NB * CC * PP];
__device__ __align__(16) float   d_qbfp[(size_t)SPLITS * NB * CC * PP];
__device__ __align__(16) float   d_tmp[NB * CC * PP];
__device__ float                 d_g1d[KS];

// ---------------- async helpers ----------------
#define CP_BULK(dst_s, src_g, nbytes, mbar_s) \
    asm volatile("cp.async.bulk.shared::cta.global.mbarrier::complete_tx::bytes [%0], [%1], %2, [%3];" \
        :: "r"(dst_s), "l"(src_g), "r"(nbytes), "r"(mbar_s) : "memory")
#define MBAR_INIT(mbar_s, cnt) \
    asm volatile("mbarrier.init.shared.b64 [%0], %1;" :: "r"(mbar_s), "r"(cnt) : "memory")
#define MBAR_EXPECT_TX(mbar_s, tx) \
    asm volatile("mbarrier.arrive.expect_tx.shared.b64 _, [%0], %1;" :: "r"(mbar_s), "r"(tx) : "memory")
#define MBAR_ARRIVE(mbar_s) \
    asm volatile("mbarrier.arrive.shared.b64 _, [%0];" :: "r"(mbar_s) : "memory")
#define MBAR_WAIT(mbar_s, parity) do { \
    asm volatile( \
        "{\n\t.reg .pred P;\n\t" \
        "WAIT_%=:\n\t" \
        "mbarrier.try_wait.parity.acquire.cta.shared::cta.b64 P, [%0], %1, 0x989680;\n\t" \
        "@P bra.uni DONE_%=;\n\t" \
        "bra.uni WAIT_%=;\n\t" \
        "DONE_%=:\n\t}" \
        :: "r"(mbar_s), "r"(parity) : "memory"); \
} while (0)

__device__ __forceinline__ void split_half(float v, __half& hi, __half& lo) {
    hi = __float2half(v);
    lo = __float2half(v - __half2float(hi));
}

__device__ __forceinline__ uint8_t* v_hi_ptr(int n, int p, int c) {
    return d_V + (size_t)(n * 64 + (p >> 6)) * V_BYTES + ((p & 63) * 24 + c) * 2;
}
__device__ __forceinline__ uint8_t* v_lo_ptr(int n, int p, int c) {
    return v_hi_ptr(n, p, c) + 3072;
}

// ---------------- fused prep: g1d + feats + U/softmax/V ----------------
__global__ void prep_kernel(const float* __restrict__ unary,
                            const float* __restrict__ ref,
                            const float* __restrict__ gk,
                            const float* __restrict__ kstd) {
    int idx = blockIdx.x * blockDim.x + threadIdx.x;
    if (blockIdx.x == 0 && threadIdx.x < KS) {
        float center = gk[KR * KS + KR];
        d_g1d[threadIdx.x] = gk[threadIdx.x * KS + KR] * rsqrtf(center);
    }
    if (idx >= NB * PP) return;
    int n = idx / PP, p = idx % PP;
    int y = p / WW, x = p % WW;

    const float* r = ref + (size_t)n * 3 * PP + p;
    d_feats[idx * 5 + 0] = (float)y / kstd[0];
    d_feats[idx * 5 + 1] = (float)x / kstd[1];
    d_feats[idx * 5 + 2] = r[0]        / kstd[2];
    d_feats[idx * 5 + 3] = r[PP]       / kstd[3];
    d_feats[idx * 5 + 4] = r[2 * PP]   / kstd[4];

    const float* u = unary + (size_t)n * CC * PP + p;
    float lg[CC];
    float m = -1e30f;
    #pragma unroll
    for (int c = 0; c < CC; ++c) {
        float v = u[(size_t)c * PP];
        v = fminf(fmaxf(v, 1e-5f), 1.0f);
        v = logf(v);
        lg[c] = v;
        m = fmaxf(m, v);
        d_U[((size_t)n * CC + c) * PP + p] = v;
    }
    float s = 0.f;
    #pragma unroll
    for (int c = 0; c < CC; ++c) { float e = expf(lg[c] - m); lg[c] = e; s += e; }
    float inv = 1.f / s;
    #pragma unroll
    for (int c = 0; c < CC; ++c) {
        float qv = lg[c] * inv;
        d_q[((size_t)n * CC + c) * PP + p] = qv;
        __half hi, lo;
        split_half(qv, hi, lo);
        *(__half*)v_hi_ptr(n, p, c) = hi;
        *(__half*)v_lo_ptr(n, p, c) = lo;
    }
    #pragma unroll
    for (int c = CC; c < 24; ++c) {
        *(__half*)v_hi_ptr(n, p, c) = __float2half(0.f);
        *(__half*)v_lo_ptr(n, p, c) = __float2half(0.f);
    }
}

// ---------------- build K (upper triangle only): fp16 + fp8 own + fp8 mirror ----------------
__global__ __launch_bounds__(256) void buildK_kernel() {
    int n  = blockIdx.z;
    int pb = blockIdx.y;
    int qc = blockIdx.x;
    if (qc < pb) return;                 // symmetric: upper triangle only

    __shared__ float fpS[64][5];
    __shared__ float fqS[64][5];
    int tid = threadIdx.x;

    for (int i = tid; i < 320; i += 256) {
        (&fpS[0][0])[i] = d_feats[((size_t)n * PP + pb * 64) * 5 + i];
        (&fqS[0][0])[i] = d_feats[((size_t)n * PP + qc * 64) * 5 + i];
    }
    __syncthreads();

    int seg = tid & 7;       // q segment (8 cols)
    int pr0 = tid >> 3;      // rows pr0 and pr0+32
    int q0  = seg << 3;
    int kk  = seg >> 1;      // q>>4
    int up  = seg & 1;       // (q>>3)&1

    float qf0[8], qf1[8], qf2[8], qf3[8], qf4[8];
    #pragma unroll
    for (int j = 0; j < 8; ++j) {
        qf0[j] = fqS[q0 + j][0];
        qf1[j] = fqS[q0 + j][1];
        qf2[j] = fqS[q0 + j][2];
        qf3[j] = fqS[q0 + j][3];
        qf4[j] = fqS[q0 + j][4];
    }

    uint8_t* tileb = d_Kt + (size_t)((n * 64 + pb) * 64 + qc) * KT_BYTES;
    bool do_mirror = (qc > pb);

    #pragma unroll
    for (int rr = 0; rr < 2; ++rr) {
        int pr = pr0 + rr * 32;
        int gid    = pr & 7;
        int half_r = (pr >> 3) & 1;
        int warp_g = pr >> 4;
        float b0 = fpS[pr][0], b1 = fpS[pr][1], b2 = fpS[pr][2],
              b3 = fpS[pr][3], b4 = fpS[pr][4];
        __align__(16) __half hbuf[8];
        float lof[8];
        #pragma unroll
        for (int j = 0; j < 8; ++j) {
            float x0 = b0 - qf0[j], x1 = b1 - qf1[j], x2 = b2 - qf2[j],
                  x3 = b3 - qf3[j], x4 = b4 - qf4[j];
            float dd = x0*x0 + x1*x1 + x2*x2 + x3*x3 + x4*x4;
            float k  = __expf(-0.5f * dd);
            __half hi = __float2half(k);
            hbuf[j] = hi;
            lof[j] = (k - __half2float(hi)) * 4096.0f;
        }
        // fp16, swizzled
        *(uint4*)(tileb + pr * 128 + ((seg ^ (pr & 7)) << 4)) = *(const uint4*)hbuf;

        // fp8 own (offset 8192), fragment-permuted
        uint32_t base8 = 8192u + (uint32_t)warp_g * 1024u + (uint32_t)kk * 256u
                       + (uint32_t)(2 * half_r + 4 * up);
        // fp8 mirror (offset 12288): addr(q_local, p_local) with own formula
        uint32_t mbase = 12288u + (uint32_t)kk * 1024u + (uint32_t)(pr >> 4) * 256u
                       + (uint32_t)(((pr & 7) >> 1) * 8) + (uint32_t)(pr & 1)
                       + (uint32_t)(up * 2) + (uint32_t)(half_r * 4);
        #pragma unroll
        for (int jj = 0; jj < 4; ++jj) {
            unsigned short pk;
            asm("cvt.rn.satfinite.e4m3x2.f32 %0, %1, %2;"
                : "=h"(pk) : "f"(lof[2 * jj + 1]), "f"(lof[2 * jj]));
            *(unsigned short*)(tileb + base8 + (uint32_t)(gid * 4 + jj) * 8u) = pk;
            if (do_mirror) {
                tileb[mbase + (uint32_t)(2 * jj) * 32u]     = (uint8_t)(pk & 0xFF);
                tileb[mbase + (uint32_t)(2 * jj + 1) * 32u] = (uint8_t)(pk >> 8);
            }
        }
    }
}

// ---- GEMM: qbf[c,p] = sum_q K[p,q]*V[q,c]; symmetric K (trans-ldmatrix for lower) ----
__global__ __launch_bounds__(128) void gemm_kernel() {
    extern __shared__ __align__(16) char dynsm[];
    __shared__ __align__(8) uint64_t mb_full[STAGES];
    __shared__ __align__(8) uint64_t mb_empty[STAGES];

    int n   = blockIdx.z;
    int spl = blockIdx.y;
    int pb  = blockIdx.x;
    int p0  = pb * BM;
    int qc0 = spl * NCH;
    int tid = threadIdx.x;
    int warp = tid >> 5, lane = tid & 31;

    uint32_t dynbase = (uint32_t)__cvta_generic_to_shared(dynsm);

    uint32_t full_s[STAGES], empty_s[STAGES];
    #pragma unroll
    for (int s = 0; s < STAGES; ++s) {
        full_s[s]  = (uint32_t)__cvta_generic_to_shared(&mb_full[s]);
        empty_s[s] = (uint32_t)__cvta_generic_to_shared(&mb_empty[s]);
    }
    if (tid == 0) {
        #pragma unroll
        for (int s = 0; s < STAGES; ++s) { MBAR_INIT(full_s[s], 1); MBAR_INIT(empty_s[s], 128); }
    }
    __syncthreads();

    const uint8_t* Vsrc = d_V + (size_t)(n * 64 + qc0) * V_BYTES;

    auto issue = [&](int ch) {
        int s = ch % STAGES;
        uint32_t sb = dynbase + s * STAGE_BYTES;
        int qc = qc0 + ch;
        int a = (pb < qc) ? pb : qc;
        int b = (pb < qc) ? qc : pb;
        const uint8_t* tile = d_Kt + (size_t)((n * 64 + a) * 64 + b) * KT_BYTES;
        MBAR_EXPECT_TX(full_s[s], (uint32_t)STAGE_BYTES);
        CP_BULK(sb,        tile, 8192u, full_s[s]);
        CP_BULK(sb + 8192, tile + (qc >= pb ? 8192 : 12288), 4096u, full_s[s]);
        CP_BULK(sb + 12288, Vsrc + (size_t)ch * V_BYTES, V_BYTES, full_s[s]);
    };

    if (tid == 0) {
        #pragma unroll
        for (int s = 0; s < STAGES; ++s) issue(s);
    }

    float acc[3][4], accl[3][4];
    #pragma unroll
    for (int i = 0; i < 3; ++i)
        #pragma unroll
        for (int j = 0; j < 4; ++j) { acc[i][j] = 0.f; accl[i][j] = 0.f; }

    int m0 = warp * 16;
    for (int ch = 0; ch < NCH; ++ch) {
        int s = ch % STAGES;
        int u = ch / STAGES;
        MBAR_WAIT(full_s[s], u & 1);
        uint32_t sb = dynbase + s * STAGE_BYTES;
        bool mirror = (qc0 + ch) < pb;

        #pragma unroll
        for (int kk = 0; kk < KC / 16; ++kk) {
            uint32_t ah0, ah1, ah2, ah3;
            if (!mirror) {
                int arow = m0 + (lane & 15);
                int aseg = (kk * 2 + (lane >> 4)) ^ (arow & 7);
                uint32_t aaddr = sb + arow * 128 + aseg * 16;
                asm volatile("ldmatrix.sync.aligned.m8n8.x4.shared.b16 {%0,%1,%2,%3}, [%4];"
                             : "=r"(ah0), "=r"(ah1), "=r"(ah2), "=r"(ah3) : "r"(aaddr));
            } else {
                int mi = lane >> 3;
                int trow = kk * 16 + ((mi >> 1) << 3) + (lane & 7);
                int tseg = ((m0 >> 3) + (mi & 1)) ^ (trow & 7);
                uint32_t aaddr = sb + trow * 128 + tseg * 16;
                asm volatile("ldmatrix.sync.aligned.m8n8.x4.trans.shared.b16 {%0,%1,%2,%3}, [%4];"
                             : "=r"(ah0), "=r"(ah1), "=r"(ah2), "=r"(ah3) : "r"(aaddr));
            }

            uint32_t aaddr_8 = sb + 8192 + warp * 1024 + kk * 256 + lane * 8;
            uint32_t w0, w1;
            asm volatile("ld.shared.v2.u32 {%0,%1}, [%2];" : "=r"(w0), "=r"(w1) : "r"(aaddr_8));
            unsigned short s0 = (unsigned short)w0, s1 = (unsigned short)(w0 >> 16);
            unsigned short s2 = (unsigned short)w1, s3 = (unsigned short)(w1 >> 16);
            uint32_t al0, al1, al2, al3;
            asm("cvt.rn.f16x2.e4m3x2 %0, %1;" : "=r"(al0) : "h"(s0));
            asm("cvt.rn.f16x2.e4m3x2 %0, %1;" : "=r"(al1) : "h"(s1));
            asm("cvt.rn.f16x2.e4m3x2 %0, %1;" : "=r"(al2) : "h"(s2));
            asm("cvt.rn.f16x2.e4m3x2 %0, %1;" : "=r"(al3) : "h"(s3));

            #pragma unroll
            for (int nt = 0; nt < 3; ++nt) {
                uint32_t baddr_h = sb + 12288 + (kk * 16 + (lane & 15)) * 48 + nt * 16;
                uint32_t baddr_l = baddr_h + 3072;
                uint32_t bh0, bh1, bl0, bl1;
                asm volatile("ldmatrix.sync.aligned.m8n8.x2.trans.shared.b16 {%0,%1}, [%2];"
                             : "=r"(bh0), "=r"(bh1) : "r"(baddr_h));
                asm volatile("ldmatrix.sync.aligned.m8n8.x2.trans.shared.b16 {%0,%1}, [%2];"
                             : "=r"(bl0), "=r"(bl1) : "r"(baddr_l));
                asm volatile(
                    "mma.sync.aligned.m16n8k16.row.col.f32.f16.f16.f32 "
                    "{%0,%1,%2,%3}, {%4,%5,%6,%7}, {%8,%9}, {%0,%1,%2,%3};"
                    : "+f"(acc[nt][0]), "+f"(acc[nt][1]), "+f"(acc[nt][2]), "+f"(acc[nt][3])
                    : "r"(ah0), "r"(ah1), "r"(ah2), "r"(ah3), "r"(bh0), "r"(bh1));
                asm volatile(
                    "mma.sync.aligned.m16n8k16.row.col.f32.f16.f16.f32 "
                    "{%0,%1,%2,%3}, {%4,%5,%6,%7}, {%8,%9}, {%0,%1,%2,%3};"
                    : "+f"(acc[nt][0]), "+f"(acc[nt][1]), "+f"(acc[nt][2]), "+f"(acc[nt][3])
                    : "r"(ah0), "r"(ah1), "r"(ah2), "r"(ah3), "r"(bl0), "r"(bl1));
                asm volatile(
                    "mma.sync.aligned.m16n8k16.row.col.f32.f16.f16.f32 "
                    "{%0,%1,%2,%3}, {%4,%5,%6,%7}, {%8,%9}, {%0,%1,%2,%3};"
                    : "+f"(accl[nt][0]), "+f"(accl[nt][1]), "+f"(accl[nt][2]), "+f"(accl[nt][3])
                    : "r"(al0), "r"(al1), "r"(al2), "r"(al3), "r"(bh0), "r"(bh1));
            }
        }

        MBAR_ARRIVE(empty_s[s]);
        if (tid == 0 && ch + STAGES < NCH) {
            MBAR_WAIT(empty_s[s], u & 1);
            issue(ch + STAGES);
        }
    }

    // epilogue: scatter partials (hi accum + scaled lo accum)
    float* qbf = d_qbfp + ((size_t)(spl * NB + n) * CC) * PP;
    int prow = p0 + warp * 16 + (lane >> 2);
    int cb = (lane & 3) * 2;
    #pragma unroll
    for (int nt = 0; nt < 3; ++nt)
        #pragma unroll
        for (int r = 0; r < 4; ++r) {
            int c = nt * 8 + cb + (r & 1);
            int p = prow + (r >> 1) * 8;
            if (c < CC) qbf[(size_t)c * PP + p] = acc[nt][r] + LO_SCALE * accl[nt][r];
        }
}

// ---------------- vertical 1-D conv on q -> tmp ----------------
__global__ void vconv_kernel() {
    int idx = blockIdx.x * blockDim.x + threadIdx.x;
    if (idx >= NB * CC * PP) return;
    int x = idx & 63, y = (idx >> 6) & 63, nc = idx >> 12;
    const float* base = d_q + (size_t)nc * PP;
    int dlo = (35 - y) > 0 ? (35 - y) : 0;
    int dhi = (98 - y) < 70 ? (98 - y) : 70;
    float acc = 0.f;
    for (int d = dlo; d <= dhi; ++d)
        acc += d_g1d[d] * base[(y + d - KR) * WW + x];
    d_tmp[idx] = acc;
}

// ---------------- horizontal conv + combine + softmax (256 threads) ----------------
__global__ __launch_bounds__(256) void hcombine_kernel(float* __restrict__ outp, int write_out) {
    __shared__ float row[CC][WW + 2 * KR];
    __shared__ float comb[CC][WW];
    __shared__ float g[KS];
    int bn = blockIdx.x;
    int n = bn >> 6, y = bn & 63;
    int tid = threadIdx.x;

    for (int i = tid; i < KS; i += 256) g[i] = d_g1d[i];
    {
        int x = tid & 63, h = tid >> 6;
        for (int c = h; c < CC; c += 4) {
            row[c][KR + x] = d_tmp[((size_t)n * CC + c) * PP + y * WW + x];
            if (x < KR) { row[c][x] = 0.f; row[c][KR + WW + x] = 0.f; }
        }
    }
    __syncthreads();

    const size_t SPL = (size_t)NB * CC * PP;
    for (int o = tid; o < CC * WW; o += 256) {
        int c = o >> 6, x = o & 63;
        float s = 0.f;
        #pragma unroll 7
        for (int d = 0; d < KS; ++d) s += g[d] * row[c][x + d];
        size_t pidx = (size_t)(n * CC + c) * PP + y * WW + x;
        float qb = 0.f;
        #pragma unroll
        for (int sp = 0; sp < SPLITS; ++sp)
            qb += d_qbfp[sp * SPL + pidx];
        comb[c][x] = d_U[pidx] + 4.0f * qb + 2.0f * s;
    }
    __syncthreads();

    if (tid < 64) {
        int x = tid;
        int p = y * WW + x;
        float lg[CC];
        float m = -1e30f;
        #pragma unroll
        for (int c = 0; c < CC; ++c) { lg[c] = comb[c][x]; m = fmaxf(m, lg[c]); }
        float ssum = 0.f;
        #pragma unroll
        for (int c = 0; c < CC; ++c) { float e = expf(lg[c] - m); lg[c] = e; ssum += e; }
        float inv = 1.f / ssum;
        #pragma unroll
        for (int c = 0; c < CC; ++c) {
            float qv = lg[c] * inv;
            size_t o = ((size_t)n * CC + c) * PP + p;
            d_q[o] = qv;
            __half hi, lo;
            split_half(qv, hi, lo);
            *(__half*)v_hi_ptr(n, p, c) = hi;
            *(__half*)v_lo_ptr(n, p, c) = lo;
            if (write_out) outp[o] = qv;
        }
    }
}

// ---------------- launch ----------------
extern "C" void kernel_launch(void* const* d_in, const int* in_sizes, int n_in,
                              void* d_out, int out_size) {
    const float* unary = (const float*)d_in[0];
    const float* ref   = (const float*)d_in[1];
    const float* gk    = (const float*)d_in[2];
    const float* kstd  = (const float*)d_in[3];
    float* out = (float*)d_out;

    cudaFuncSetAttribute(gemm_kernel, cudaFuncAttributeMaxDynamicSharedMemorySize, SMEM_DYN);

    prep_kernel<<<(NB * PP + 255) / 256, 256>>>(unary, ref, gk, kstd);
    buildK_kernel<<<dim3(64, 64, NB), 256>>>();

    for (int it = 0; it < 5; ++it) {
        vconv_kernel<<<(NB * CC * PP + 255) / 256, 256>>>();
        gemm_kernel<<<dim3(PP / BM, SPLITS, NB), 128, SMEM_DYN>>>();
        hcombine_kernel<<<NB * HH, 256>>>(out, it == 4 ? 1 : 0);
    }
}